// round 11
// baseline (speedup 1.0000x reference)
#include <cuda_runtime.h>
#include <math.h>
#include <stdint.h>

#define NN    10000
#define EEMAX 320000
#define ETOTM (EEMAX + NN)

// ---------------- scratch: double-buffered per branch ----------------
__device__ __align__(16) float g_h1[2 * NN * 384];
__device__ __align__(16) float g_s1[2 * NN * 3];
__device__ __align__(16) float g_d1[2 * NN * 3];
__device__ __align__(16) float g_agg1[2 * NN * 384];
__device__ __align__(16) float g_h2[2 * NN * 128];
__device__ __align__(16) float g_s2[2 * NN];
__device__ __align__(16) float g_d2[2 * NN];
__device__ __align__(16) float g_exp1[2 * 3 * ETOTM];
__device__ __align__(16) float g_exp2[2 * ETOTM];
__device__ __align__(16) float g_agg2[2 * NN * 128];
__device__ __align__(16) float g_nattn[2 * NN];
__device__ __align__(16) float g_pool[2 * 256];
// CSR per branch
__device__ int g_deg[2 * NN];
__device__ int g_off[2 * (NN + 1)];
__device__ int g_fill[2 * NN];
__device__ int g_eid[2 * ETOTM];
__device__ int g_esrc[2 * ETOTM];

// ---------------- CSR build ----------------
__global__ void init_deg(int Ncnt)
{
    int i = blockIdx.x * blockDim.x + threadIdx.x;
    if (i < 2 * Ncnt) g_deg[i] = 0;
}

__global__ void csr_count(const int* __restrict__ ei1, const int* __restrict__ ei2,
                          int E, int Ncnt)
{
    int t = blockIdx.x * blockDim.x + threadIdx.x;
    int Etot = E + Ncnt;
    if (t >= 2 * Etot) return;
    int b = (t >= Etot) ? 1 : 0;
    int e = t - b * Etot;
    const int* ei = b ? ei2 : ei1;
    int dst = (e < E) ? ei[E + e] : (e - E);
    dst = min(max(dst, 0), Ncnt - 1);
    atomicAdd(&g_deg[b * NN + dst], 1);
}

__global__ void csr_scan(int Ncnt, int Etot)
{
    __shared__ int part[1024];
    int b = blockIdx.x;
    int* deg = g_deg + b * NN;
    int* off = g_off + b * (NN + 1);
    int* fil = g_fill + b * NN;
    int t = threadIdx.x;
    int chunk = (Ncnt + 1023) / 1024;
    int s0 = t * chunk;
    int s1 = min(s0 + chunk, Ncnt);
    int s = 0;
    for (int i = s0; i < s1; i++) s += deg[i];
    part[t] = s;
    __syncthreads();
    for (int o = 1; o < 1024; o <<= 1) {
        int v = (t >= o) ? part[t - o] : 0;
        __syncthreads();
        part[t] += v;
        __syncthreads();
    }
    int run = part[t] - s;
    for (int i = s0; i < s1; i++) {
        off[i] = run;
        fil[i] = run;
        run += deg[i];
    }
    if (t == 0) off[Ncnt] = Etot;
}

__global__ void csr_scatter(const int* __restrict__ ei1, const int* __restrict__ ei2,
                            int E, int Ncnt)
{
    int t = blockIdx.x * blockDim.x + threadIdx.x;
    int Etot = E + Ncnt;
    if (t >= 2 * Etot) return;
    int b = (t >= Etot) ? 1 : 0;
    int e = t - b * Etot;
    const int* ei = b ? ei2 : ei1;
    int src, dst;
    if (e < E) { src = ei[e]; dst = ei[E + e]; }
    else       { src = e - E; dst = src; }
    src = min(max(src, 0), Ncnt - 1);
    dst = min(max(dst, 0), Ncnt - 1);
    int pos = atomicAdd(&g_fill[b * NN + dst], 1);
    g_eid[b * ETOTM + pos] = e;
    g_esrc[b * ETOTM + pos] = src;
}

// ---------------- GEMM1 + fused sd_l1 ----------------
// h1[b][M,384] = x_b[M,256] @ W1[256,384]; blockIdx.x = head (BN=128 = one head),
// blockIdx.z = branch. Double-buffered SMEM, 1 sync/iter. Epilogue computes
// s1/d1 = h . att (block-local reduction, no separate kernel).
__global__ __launch_bounds__(256) void gemm_l1(const float* __restrict__ A1,
                                               const float* __restrict__ A2,
                                               const float* __restrict__ B,
                                               const float* __restrict__ asrc,
                                               const float* __restrict__ adst, int M)
{
    const int N = 384, K = 256, NIT = K / 8;
    __shared__ float As[2][8][132];
    __shared__ float Bs[2][8][128];
    __shared__ float Sred[128][17];
    const int tid = threadIdx.x;
    const int tx = tid & 15, ty = tid >> 4;
    const int head = blockIdx.x;
    const int row0 = blockIdx.y * 128, col0 = head * 128;
    const int bb = blockIdx.z;
    const float* A = bb ? A2 : A1;
    float* H = g_h1 + (size_t)bb * NN * 384;

    const int ar = tid >> 1, ac = (tid & 1) * 4;
    const int br = tid >> 5, bc = (tid & 31) * 4;
    const int arow = row0 + ar;

    // preload tile 0
    {
        float4 av = make_float4(0.f, 0.f, 0.f, 0.f);
        if (arow < M) av = *(const float4*)(A + (size_t)arow * K + ac);
        As[0][ac + 0][ar] = av.x; As[0][ac + 1][ar] = av.y;
        As[0][ac + 2][ar] = av.z; As[0][ac + 3][ar] = av.w;
        *(float4*)&Bs[0][br][bc] = *(const float4*)(B + (size_t)br * N + col0 + bc);
    }
    __syncthreads();

    float acc[8][8] = {};
    for (int it = 0; it < NIT; it++) {
        int cur = it & 1;
        float4 pav = make_float4(0.f, 0.f, 0.f, 0.f), pbv;
        bool more = (it + 1 < NIT);
        if (more) {
            int k0 = (it + 1) * 8;
            if (arow < M) pav = *(const float4*)(A + (size_t)arow * K + k0 + ac);
            pbv = *(const float4*)(B + (size_t)(k0 + br) * N + col0 + bc);
        }
        const float (*Ac)[132] = As[cur];
        const float (*Bc)[128] = Bs[cur];
        #pragma unroll
        for (int k = 0; k < 8; k++) {
            float a[8], b[8];
            #pragma unroll
            for (int i = 0; i < 8; i++) a[i] = Ac[k][ty * 8 + i];
            #pragma unroll
            for (int j = 0; j < 8; j++) b[j] = Bc[k][tx * 8 + j];
            #pragma unroll
            for (int i = 0; i < 8; i++)
                #pragma unroll
                for (int j = 0; j < 8; j++)
                    acc[i][j] += a[i] * b[j];
        }
        if (more) {
            int nxt = cur ^ 1;
            As[nxt][ac + 0][ar] = pav.x; As[nxt][ac + 1][ar] = pav.y;
            As[nxt][ac + 2][ar] = pav.z; As[nxt][ac + 3][ar] = pav.w;
            *(float4*)&Bs[nxt][br][bc] = pbv;
        }
        __syncthreads();
    }

    // write H
    #pragma unroll
    for (int i = 0; i < 8; i++) {
        int row = row0 + ty * 8 + i;
        if (row < M) {
            *(float4*)(H + (size_t)row * N + col0 + tx * 8) =
                make_float4(acc[i][0], acc[i][1], acc[i][2], acc[i][3]);
            *(float4*)(H + (size_t)row * N + col0 + tx * 8 + 4) =
                make_float4(acc[i][4], acc[i][5], acc[i][6], acc[i][7]);
        }
    }

    // fused sd: s = h . asrc[head], d = h . adst[head]
    float as_c[8], ad_c[8];
    #pragma unroll
    for (int j = 0; j < 8; j++) {
        as_c[j] = asrc[head * 128 + tx * 8 + j];
        ad_c[j] = adst[head * 128 + tx * 8 + j];
    }
    // pass 1: s
    #pragma unroll
    for (int i = 0; i < 8; i++) {
        float p = 0.f;
        #pragma unroll
        for (int j = 0; j < 8; j++) p += acc[i][j] * as_c[j];
        Sred[ty * 8 + i][tx] = p;
    }
    __syncthreads();
    if (tid < 128) {
        float s = 0.f;
        #pragma unroll
        for (int t = 0; t < 16; t++) s += Sred[tid][t];
        int row = row0 + tid;
        if (row < M) g_s1[(size_t)bb * NN * 3 + row * 3 + head] = s;
    }
    __syncthreads();
    // pass 2: d
    #pragma unroll
    for (int i = 0; i < 8; i++) {
        float p = 0.f;
        #pragma unroll
        for (int j = 0; j < 8; j++) p += acc[i][j] * ad_c[j];
        Sred[ty * 8 + i][tx] = p;
    }
    __syncthreads();
    if (tid < 128) {
        float d = 0.f;
        #pragma unroll
        for (int t = 0; t < 16; t++) d += Sred[tid][t];
        int row = row0 + tid;
        if (row < M) g_d1[(size_t)bb * NN * 3 + row * 3 + head] = d;
    }
}

// ---------------- GEMM2: h2[b][M,128] = relu(agg1[b]+b1)[M,384] @ W2 ----------
// BM=128, BN=64, BK=8, double-buffered.
__global__ __launch_bounds__(256) void gemm_l2(const float* __restrict__ B,
                                               const float* __restrict__ abias, int M)
{
    const int N = 128, K = 384, NIT = K / 8;
    __shared__ float As[2][8][132];
    __shared__ float Bs[2][8][64];
    const int tid = threadIdx.x;
    const int tx = tid & 15, ty = tid >> 4;
    const int row0 = blockIdx.y * 128, col0 = blockIdx.x * 64;
    const float* AG = g_agg1 + (size_t)blockIdx.z * NN * 384;
    float* H = g_h2 + (size_t)blockIdx.z * NN * 128;

    const int ar = tid >> 1, ac = (tid & 1) * 4;
    const int arow = row0 + ar;
    const int br = tid >> 4, bc = (tid & 15) * 4;   // tid<128 loads B

    {
        float4 av = make_float4(0.f, 0.f, 0.f, 0.f);
        if (arow < M) {
            av = *(const float4*)(AG + (size_t)arow * K + ac);
            av.x = fmaxf(av.x + abias[ac + 0], 0.f);
            av.y = fmaxf(av.y + abias[ac + 1], 0.f);
            av.z = fmaxf(av.z + abias[ac + 2], 0.f);
            av.w = fmaxf(av.w + abias[ac + 3], 0.f);
        }
        As[0][ac + 0][ar] = av.x; As[0][ac + 1][ar] = av.y;
        As[0][ac + 2][ar] = av.z; As[0][ac + 3][ar] = av.w;
        if (tid < 128)
            *(float4*)&Bs[0][br][bc] = *(const float4*)(B + (size_t)br * N + col0 + bc);
    }
    __syncthreads();

    float acc[8][4] = {};
    for (int it = 0; it < NIT; it++) {
        int cur = it & 1;
        float4 pav = make_float4(0.f, 0.f, 0.f, 0.f), pbv;
        bool more = (it + 1 < NIT);
        if (more) {
            int k0 = (it + 1) * 8;
            if (arow < M) {
                pav = *(const float4*)(AG + (size_t)arow * K + k0 + ac);
                pav.x = fmaxf(pav.x + abias[k0 + ac + 0], 0.f);
                pav.y = fmaxf(pav.y + abias[k0 + ac + 1], 0.f);
                pav.z = fmaxf(pav.z + abias[k0 + ac + 2], 0.f);
                pav.w = fmaxf(pav.w + abias[k0 + ac + 3], 0.f);
            }
            if (tid < 128)
                pbv = *(const float4*)(B + (size_t)(k0 + br) * N + col0 + bc);
        }
        const float (*Ac)[132] = As[cur];
        const float (*Bc)[64] = Bs[cur];
        #pragma unroll
        for (int k = 0; k < 8; k++) {
            float a[8], b[4];
            #pragma unroll
            for (int i = 0; i < 8; i++) a[i] = Ac[k][ty * 8 + i];
            #pragma unroll
            for (int j = 0; j < 4; j++) b[j] = Bc[k][tx * 4 + j];
            #pragma unroll
            for (int i = 0; i < 8; i++)
                #pragma unroll
                for (int j = 0; j < 4; j++)
                    acc[i][j] += a[i] * b[j];
        }
        if (more) {
            int nxt = cur ^ 1;
            As[nxt][ac + 0][ar] = pav.x; As[nxt][ac + 1][ar] = pav.y;
            As[nxt][ac + 2][ar] = pav.z; As[nxt][ac + 3][ar] = pav.w;
            if (tid < 128) *(float4*)&Bs[nxt][br][bc] = pbv;
        }
        __syncthreads();
    }
    #pragma unroll
    for (int i = 0; i < 8; i++) {
        int row = row0 + ty * 8 + i;
        if (row < M)
            *(float4*)(H + (size_t)row * N + col0 + tx * 4) =
                make_float4(acc[i][0], acc[i][1], acc[i][2], acc[i][3]);
    }
}

// ---------------- sd_l2: warp per (b, node) ----------------
__global__ void sd_l2(const float* __restrict__ asrc, const float* __restrict__ adst, int n)
{
    int w = (blockIdx.x * blockDim.x + threadIdx.x) >> 5;
    int lane = threadIdx.x & 31;
    if (w >= 2 * n) return;
    int b = w / n;
    int loc = w - b * n;
    float4 hv = *(const float4*)(g_h2 + ((size_t)b * NN + loc) * 128 + lane * 4);
    float4 sa = *(const float4*)(asrc + lane * 4);
    float4 da = *(const float4*)(adst + lane * 4);
    float ss = hv.x * sa.x + hv.y * sa.y + hv.z * sa.z + hv.w * sa.w;
    float dd = hv.x * da.x + hv.y * da.y + hv.z * da.z + hv.w * da.w;
    #pragma unroll
    for (int o = 16; o; o >>= 1) {
        ss += __shfl_down_sync(0xffffffffu, ss, o);
        dd += __shfl_down_sync(0xffffffffu, dd, o);
    }
    if (lane == 0) { g_s2[b * NN + loc] = ss; g_d2[b * NN + loc] = dd; }
}

// ---------------- layer-1 softmax + aggregation ----------------
__global__ __launch_bounds__(256) void agg_l1_csr(int E, int Ncnt,
                                                  float* __restrict__ out, long long out_size)
{
    int b = blockIdx.y;
    int dst = (blockIdx.x * blockDim.x + threadIdx.x) >> 5;
    int lane = threadIdx.x & 31;
    if (dst >= Ncnt) return;
    const int Etot = E + Ncnt;
    const int* off  = g_off + b * (NN + 1);
    const int* eidv = g_eid + b * ETOTM;
    const int* srcv = g_esrc + b * ETOTM;
    const float* s1 = g_s1 + b * NN * 3;
    float* e0p = g_exp1 + (size_t)(b * 3 + 0) * ETOTM;
    float* e1p = g_exp1 + (size_t)(b * 3 + 1) * ETOTM;
    float* e2p = g_exp1 + (size_t)(b * 3 + 2) * ETOTM;
    const long long alpha_base = 1 + (long long)b * Etot * 3;

    int beg = off[dst], end = off[dst + 1];
    float dv0 = g_d1[b * NN * 3 + dst * 3 + 0];
    float dv1 = g_d1[b * NN * 3 + dst * 3 + 1];
    float dv2 = g_d1[b * NN * 3 + dst * 3 + 2];

    float den0 = 0.f, den1 = 0.f, den2 = 0.f;
    for (int i = beg + lane; i < end; i += 32) {
        int src = srcv[i];
        float e0 = s1[src * 3 + 0] + dv0;
        float e1 = s1[src * 3 + 1] + dv1;
        float e2 = s1[src * 3 + 2] + dv2;
        e0 = e0 > 0.f ? e0 : 0.2f * e0;
        e1 = e1 > 0.f ? e1 : 0.2f * e1;
        e2 = e2 > 0.f ? e2 : 0.2f * e2;
        float x0 = expf(e0), x1 = expf(e1), x2 = expf(e2);
        e0p[i] = x0; e1p[i] = x1; e2p[i] = x2;
        den0 += x0; den1 += x1; den2 += x2;
    }
    #pragma unroll
    for (int o = 16; o; o >>= 1) {
        den0 += __shfl_xor_sync(0xffffffffu, den0, o);
        den1 += __shfl_xor_sync(0xffffffffu, den1, o);
        den2 += __shfl_xor_sync(0xffffffffu, den2, o);
    }
    float r0 = 1.f / den0, r1 = 1.f / den1, r2 = 1.f / den2;
    __syncwarp();

    float nat = 0.f;
    for (int i = beg + lane; i < end; i += 32) {
        float a0 = e0p[i] * r0, a1 = e1p[i] * r1, a2 = e2p[i] * r2;
        long long ob = alpha_base + 3LL * eidv[i];
        if (ob + 2 < out_size) { out[ob] = a0; out[ob + 1] = a1; out[ob + 2] = a2; }
        nat += (a0 + a1 + a2) * (1.0f / 3.0f);
    }
    #pragma unroll
    for (int o = 16; o; o >>= 1) nat += __shfl_xor_sync(0xffffffffu, nat, o);
    if (lane == 0) g_nattn[b * NN + dst] = nat;

    float acc[12];
    #pragma unroll
    for (int k = 0; k < 12; k++) acc[k] = 0.f;
    const float4* h1b = (const float4*)(g_h1 + (size_t)b * NN * 384);

    #pragma unroll 2
    for (int i = beg; i < end; i++) {
        float a0 = e0p[i] * r0, a1 = e1p[i] * r1, a2 = e2p[i] * r2;
        int src = srcv[i];
        const float4* hs = h1b + (size_t)src * 96;
        float4 v0 = hs[lane];
        float4 v1 = hs[32 + lane];
        float4 v2 = hs[64 + lane];
        acc[0] += v0.x * a0; acc[1]  += v0.y * a0; acc[2]  += v0.z * a0; acc[3]  += v0.w * a0;
        acc[4] += v1.x * a1; acc[5]  += v1.y * a1; acc[6]  += v1.z * a1; acc[7]  += v1.w * a1;
        acc[8] += v2.x * a2; acc[9]  += v2.y * a2; acc[10] += v2.z * a2; acc[11] += v2.w * a2;
    }

    float4* og = (float4*)(g_agg1 + ((size_t)b * NN + dst) * 384);
    og[lane]      = make_float4(acc[0], acc[1], acc[2], acc[3]);
    og[32 + lane] = make_float4(acc[4], acc[5], acc[6], acc[7]);
    og[64 + lane] = make_float4(acc[8], acc[9], acc[10], acc[11]);
}

// ---------------- layer-2 softmax + aggregation ----------------
__global__ __launch_bounds__(256) void agg_l2_csr(int E, int Ncnt)
{
    int b = blockIdx.y;
    int dst = (blockIdx.x * blockDim.x + threadIdx.x) >> 5;
    int lane = threadIdx.x & 31;
    if (dst >= Ncnt) return;
    const int* off  = g_off + b * (NN + 1);
    const int* srcv = g_esrc + b * ETOTM;
    const float* s2 = g_s2 + b * NN;
    float* xp = g_exp2 + (size_t)b * ETOTM;

    int beg = off[dst], end = off[dst + 1];
    float dv = g_d2[b * NN + dst];
    float den = 0.f;
    for (int i = beg + lane; i < end; i += 32) {
        int src = srcv[i];
        float e = s2[src] + dv;
        e = e > 0.f ? e : 0.2f * e;
        float x = expf(e);
        xp[i] = x;
        den += x;
    }
    #pragma unroll
    for (int o = 16; o; o >>= 1) den += __shfl_xor_sync(0xffffffffu, den, o);
    float r = 1.f / den;
    __syncwarp();

    float4 acc = make_float4(0.f, 0.f, 0.f, 0.f);
    const float4* h2b = (const float4*)(g_h2 + (size_t)b * NN * 128);
    #pragma unroll 2
    for (int i = beg; i < end; i++) {
        float a = xp[i] * r;
        int src = srcv[i];
        float4 v = h2b[(size_t)src * 32 + lane];
        acc.x += v.x * a; acc.y += v.y * a; acc.z += v.z * a; acc.w += v.w * a;
    }
    ((float4*)(g_agg2 + ((size_t)b * NN + dst) * 128))[lane] = acc;
}

// ---------------- pooling: grid (128, 2) ----------------
__global__ void pool_kernel(const float* __restrict__ b2, int Ncnt)
{
    int c = blockIdx.x;
    int b = blockIdx.y;
    const float* ag = g_agg2 + (size_t)b * NN * 128;
    const float* na = g_nattn + b * NN;
    float bias = b2[c];
    float sw = 0.f, se = 0.f;
    for (int n = threadIdx.x; n < Ncnt; n += blockDim.x) {
        float v = ag[(size_t)n * 128 + c] + bias;
        se += v;
        sw += v * na[n];
    }
    __shared__ float r0[256], r1[256];
    r0[threadIdx.x] = sw; r1[threadIdx.x] = se;
    __syncthreads();
    for (int o = 128; o; o >>= 1) {
        if (threadIdx.x < o) { r0[threadIdx.x] += r0[threadIdx.x + o]; r1[threadIdx.x] += r1[threadIdx.x + o]; }
        __syncthreads();
    }
    if (threadIdx.x == 0) {
        float inv = 1.0f / (float)Ncnt;
        g_pool[b * 256 + c]       = r0[0] * inv;
        g_pool[b * 256 + 128 + c] = r1[0] * inv;
    }
}

// ---------------- cosine similarity ----------------
__global__ void sim_kernel(float* __restrict__ out, long long out_size)
{
    int t = threadIdx.x;
    float a = g_pool[t], b = g_pool[256 + t];
    __shared__ float sd_[256], sa[256], sb[256];
    sd_[t] = a * b; sa[t] = a * a; sb[t] = b * b;
    __syncthreads();
    for (int o = 128; o; o >>= 1) {
        if (t < o) { sd_[t] += sd_[t + o]; sa[t] += sa[t + o]; sb[t] += sb[t + o]; }
        __syncthreads();
    }
    if (t == 0 && out_size >= 1) {
        float n1 = fmaxf(sqrtf(sa[0]), 1e-8f);
        float n2 = fmaxf(sqrtf(sb[0]), 1e-8f);
        out[0] = sd_[0] / (n1 * n2);
    }
}

// ---------------- host launcher ----------------
extern "C" void kernel_launch(void* const* d_in, const int* in_sizes, int n_in,
                              void* d_out, int out_size)
{
    const float* x1  = (const float*)d_in[0];
    const int*   ei1 = (const int*)d_in[1];     // int32
    const float* x2  = (const float*)d_in[2];
    const int*   ei2 = (const int*)d_in[3];
    const float* W1  = (const float*)d_in[4];
    const float* as1 = (const float*)d_in[5];
    const float* ad1 = (const float*)d_in[6];
    const float* b1  = (const float*)d_in[7];
    const float* W2  = (const float*)d_in[8];
    const float* as2 = (const float*)d_in[9];
    const float* ad2 = (const float*)d_in[10];
    const float* b2  = (const float*)d_in[11];
    float* out = (float*)d_out;
    const long long osz = (long long)out_size;

    const int Ncnt = in_sizes[0] / 256;
    const int E    = in_sizes[1] / 2;
    const int Etot = E + Ncnt;

    const int e2blocks = (2 * Etot + 255) / 256;
    const int nwb = (Ncnt * 32 + 255) / 256;

    // CSR build, both branches fused
    init_deg<<<(2 * Ncnt + 255) / 256, 256>>>(Ncnt);
    csr_count<<<e2blocks, 256>>>(ei1, ei2, E, Ncnt);
    csr_scan<<<2, 1024>>>(Ncnt, Etot);
    csr_scatter<<<e2blocks, 256>>>(ei1, ei2, E, Ncnt);

    // layer 1 (both branches); sd_l1 fused into gemm_l1 epilogue
    gemm_l1<<<dim3(3, (Ncnt + 127) / 128, 2), 256>>>(x1, x2, W1, as1, ad1, Ncnt);
    agg_l1_csr<<<dim3(nwb, 2), 256>>>(E, Ncnt, out, osz);

    // layer 2 (both branches)
    gemm_l2<<<dim3(2, (Ncnt + 127) / 128, 2), 256>>>(W2, b1, Ncnt);
    sd_l2<<<(2 * Ncnt * 32 + 255) / 256, 256>>>(as2, ad2, Ncnt);
    agg_l2_csr<<<dim3(nwb, 2), 256>>>(E, Ncnt);

    // pooling + similarity
    pool_kernel<<<dim3(128, 2), 256>>>(b2, Ncnt);
    sim_kernel<<<1, 256>>>(out, osz);
}

// round 13
// speedup vs baseline: 1.0833x; 1.0833x over previous
#include <cuda_runtime.h>
#include <math.h>
#include <stdint.h>

#define NN    10000
#define EEMAX 320000
#define ETOTM (EEMAX + NN)

// ---------------- scratch: double-buffered per branch ----------------
__device__ __align__(16) float g_h1[2 * NN * 384];
__device__ __align__(16) float g_s1[2 * NN * 3];
__device__ __align__(16) float g_d1[2 * NN * 3];
__device__ __align__(16) float g_agg1[2 * NN * 384];
__device__ __align__(16) float g_h2[2 * NN * 128];
__device__ __align__(16) float g_s2[2 * NN];
__device__ __align__(16) float g_d2[2 * NN];
__device__ __align__(16) float g_exp1[2 * 3 * ETOTM];
__device__ __align__(16) float g_exp2[2 * ETOTM];
__device__ __align__(16) float g_agg2[2 * NN * 128];
__device__ __align__(16) float g_nattn[2 * NN];
__device__ __align__(16) float g_pool[2 * 256];
// CSR per branch
__device__ int g_deg[2 * NN];
__device__ int g_off[2 * (NN + 1)];
__device__ int g_fill[2 * NN];
__device__ int g_eid[2 * ETOTM];
__device__ int g_esrc[2 * ETOTM];

// ---------------- CSR build ----------------
__global__ void init_deg(int Ncnt)
{
    int i = blockIdx.x * blockDim.x + threadIdx.x;
    if (i < 2 * Ncnt) g_deg[i] = 0;
}

__global__ void csr_count(const int* __restrict__ ei1, const int* __restrict__ ei2,
                          int E, int Ncnt)
{
    int t = blockIdx.x * blockDim.x + threadIdx.x;
    int Etot = E + Ncnt;
    if (t >= 2 * Etot) return;
    int b = (t >= Etot) ? 1 : 0;
    int e = t - b * Etot;
    const int* ei = b ? ei2 : ei1;
    int dst = (e < E) ? ei[E + e] : (e - E);
    dst = min(max(dst, 0), Ncnt - 1);
    atomicAdd(&g_deg[b * NN + dst], 1);
}

__global__ void csr_scan(int Ncnt, int Etot)
{
    __shared__ int part[1024];
    int b = blockIdx.x;
    int* deg = g_deg + b * NN;
    int* off = g_off + b * (NN + 1);
    int* fil = g_fill + b * NN;
    int t = threadIdx.x;
    int chunk = (Ncnt + 1023) / 1024;
    int s0 = t * chunk;
    int s1 = min(s0 + chunk, Ncnt);
    int s = 0;
    for (int i = s0; i < s1; i++) s += deg[i];
    part[t] = s;
    __syncthreads();
    for (int o = 1; o < 1024; o <<= 1) {
        int v = (t >= o) ? part[t - o] : 0;
        __syncthreads();
        part[t] += v;
        __syncthreads();
    }
    int run = part[t] - s;
    for (int i = s0; i < s1; i++) {
        off[i] = run;
        fil[i] = run;
        run += deg[i];
    }
    if (t == 0) off[Ncnt] = Etot;
}

__global__ void csr_scatter(const int* __restrict__ ei1, const int* __restrict__ ei2,
                            int E, int Ncnt)
{
    int t = blockIdx.x * blockDim.x + threadIdx.x;
    int Etot = E + Ncnt;
    if (t >= 2 * Etot) return;
    int b = (t >= Etot) ? 1 : 0;
    int e = t - b * Etot;
    const int* ei = b ? ei2 : ei1;
    int src, dst;
    if (e < E) { src = ei[e]; dst = ei[E + e]; }
    else       { src = e - E; dst = src; }
    src = min(max(src, 0), Ncnt - 1);
    dst = min(max(dst, 0), Ncnt - 1);
    int pos = atomicAdd(&g_fill[b * NN + dst], 1);
    g_eid[b * ETOTM + pos] = e;
    g_esrc[b * ETOTM + pos] = src;
}

// ---------------- GEMM1: h1[b][M,384] = x_b[M,256] @ W1[256,384] ----------------
// BM=128, BN=128, BK=16, 256 threads, 8x8 microtile, single-buffered.
__global__ __launch_bounds__(256) void gemm_l1(const float* __restrict__ A1,
                                               const float* __restrict__ A2,
                                               const float* __restrict__ B, int M)
{
    const int N = 384, K = 256;
    __shared__ float As[16][132];
    __shared__ float Bs[16][128];
    const int tid = threadIdx.x;
    const int tx = tid & 15, ty = tid >> 4;
    const int row0 = blockIdx.y * 128, col0 = blockIdx.x * 128;
    const float* A = blockIdx.z ? A2 : A1;
    float* H = g_h1 + (size_t)blockIdx.z * NN * 384;
    float acc[8][8] = {};

    const int ar = tid >> 1, ac = (tid & 1) * 8;   // 2 float4 per thread (A)
    const int br = tid >> 4, bc = (tid & 15) * 8;  // 2 float4 per thread (B)
    const int arow = row0 + ar;

    for (int k0 = 0; k0 < K; k0 += 16) {
        {
            float4 a0 = make_float4(0.f, 0.f, 0.f, 0.f), a1 = a0;
            if (arow < M) {
                a0 = *(const float4*)(A + (size_t)arow * K + k0 + ac);
                a1 = *(const float4*)(A + (size_t)arow * K + k0 + ac + 4);
            }
            As[ac + 0][ar] = a0.x; As[ac + 1][ar] = a0.y;
            As[ac + 2][ar] = a0.z; As[ac + 3][ar] = a0.w;
            As[ac + 4][ar] = a1.x; As[ac + 5][ar] = a1.y;
            As[ac + 6][ar] = a1.z; As[ac + 7][ar] = a1.w;

            *(float4*)&Bs[br][bc]     = *(const float4*)(B + (size_t)(k0 + br) * N + col0 + bc);
            *(float4*)&Bs[br][bc + 4] = *(const float4*)(B + (size_t)(k0 + br) * N + col0 + bc + 4);
        }
        __syncthreads();

        #pragma unroll
        for (int k = 0; k < 16; k++) {
            float a[8], b[8];
            #pragma unroll
            for (int i = 0; i < 8; i++) a[i] = As[k][ty * 8 + i];
            #pragma unroll
            for (int j = 0; j < 8; j++) b[j] = Bs[k][tx * 8 + j];
            #pragma unroll
            for (int i = 0; i < 8; i++)
                #pragma unroll
                for (int j = 0; j < 8; j++)
                    acc[i][j] += a[i] * b[j];
        }
        __syncthreads();
    }
    #pragma unroll
    for (int i = 0; i < 8; i++) {
        int row = row0 + ty * 8 + i;
        if (row < M) {
            *(float4*)(H + (size_t)row * N + col0 + tx * 8) =
                make_float4(acc[i][0], acc[i][1], acc[i][2], acc[i][3]);
            *(float4*)(H + (size_t)row * N + col0 + tx * 8 + 4) =
                make_float4(acc[i][4], acc[i][5], acc[i][6], acc[i][7]);
        }
    }
}

// ---------------- GEMM2: h2[b][M,128] = relu(agg1[b]+b1)[M,384] @ W2 ----------
// BM=128, BN=64, BK=16, 256 threads, 8x4 microtile, single-buffered.
__global__ __launch_bounds__(256) void gemm_l2(const float* __restrict__ B,
                                               const float* __restrict__ abias, int M)
{
    const int N = 128, K = 384;
    __shared__ float As[16][132];
    __shared__ float Bs[16][64];
    const int tid = threadIdx.x;
    const int tx = tid & 15, ty = tid >> 4;
    const int row0 = blockIdx.y * 128, col0 = blockIdx.x * 64;
    const float* AG = g_agg1 + (size_t)blockIdx.z * NN * 384;
    float* H = g_h2 + (size_t)blockIdx.z * NN * 128;
    float acc[8][4] = {};

    const int ar = tid >> 1, ac = (tid & 1) * 8;
    const int arow = row0 + ar;
    const int br = tid >> 4, bc = (tid & 15) * 4;  // 1 float4 per thread (B)

    for (int k0 = 0; k0 < K; k0 += 16) {
        {
            float4 a0 = make_float4(0.f, 0.f, 0.f, 0.f), a1 = a0;
            if (arow < M) {
                a0 = *(const float4*)(AG + (size_t)arow * K + k0 + ac);
                a1 = *(const float4*)(AG + (size_t)arow * K + k0 + ac + 4);
                a0.x = fmaxf(a0.x + abias[k0 + ac + 0], 0.f);
                a0.y = fmaxf(a0.y + abias[k0 + ac + 1], 0.f);
                a0.z = fmaxf(a0.z + abias[k0 + ac + 2], 0.f);
                a0.w = fmaxf(a0.w + abias[k0 + ac + 3], 0.f);
                a1.x = fmaxf(a1.x + abias[k0 + ac + 4], 0.f);
                a1.y = fmaxf(a1.y + abias[k0 + ac + 5], 0.f);
                a1.z = fmaxf(a1.z + abias[k0 + ac + 6], 0.f);
                a1.w = fmaxf(a1.w + abias[k0 + ac + 7], 0.f);
            }
            As[ac + 0][ar] = a0.x; As[ac + 1][ar] = a0.y;
            As[ac + 2][ar] = a0.z; As[ac + 3][ar] = a0.w;
            As[ac + 4][ar] = a1.x; As[ac + 5][ar] = a1.y;
            As[ac + 6][ar] = a1.z; As[ac + 7][ar] = a1.w;

            *(float4*)&Bs[br][bc] = *(const float4*)(B + (size_t)(k0 + br) * N + col0 + bc);
        }
        __syncthreads();

        #pragma unroll
        for (int k = 0; k < 16; k++) {
            float a[8], b[4];
            #pragma unroll
            for (int i = 0; i < 8; i++) a[i] = As[k][ty * 8 + i];
            #pragma unroll
            for (int j = 0; j < 4; j++) b[j] = Bs[k][tx * 4 + j];
            #pragma unroll
            for (int i = 0; i < 8; i++)
                #pragma unroll
                for (int j = 0; j < 4; j++)
                    acc[i][j] += a[i] * b[j];
        }
        __syncthreads();
    }
    #pragma unroll
    for (int i = 0; i < 8; i++) {
        int row = row0 + ty * 8 + i;
        if (row < M)
            *(float4*)(H + (size_t)row * N + col0 + tx * 4) =
                make_float4(acc[i][0], acc[i][1], acc[i][2], acc[i][3]);
    }
}

// ---------------- s/d (both branches): warp per (b, node, head) ---------------
__global__ void sd_l1(const float* __restrict__ asrc, const float* __restrict__ adst, int n)
{
    int w = (blockIdx.x * blockDim.x + threadIdx.x) >> 5;
    int lane = threadIdx.x & 31;
    if (w >= 2 * n * 3) return;
    int b = w / (n * 3);
    int loc = w - b * n * 3;
    int hd = loc % 3;
    float4 hv = *(const float4*)(g_h1 + ((size_t)b * NN * 3 + loc) * 128 + lane * 4);
    float4 sa = *(const float4*)(asrc + hd * 128 + lane * 4);
    float4 da = *(const float4*)(adst + hd * 128 + lane * 4);
    float ss = hv.x * sa.x + hv.y * sa.y + hv.z * sa.z + hv.w * sa.w;
    float dd = hv.x * da.x + hv.y * da.y + hv.z * da.z + hv.w * da.w;
    #pragma unroll
    for (int o = 16; o; o >>= 1) {
        ss += __shfl_down_sync(0xffffffffu, ss, o);
        dd += __shfl_down_sync(0xffffffffu, dd, o);
    }
    if (lane == 0) { g_s1[b * NN * 3 + loc] = ss; g_d1[b * NN * 3 + loc] = dd; }
}

__global__ void sd_l2(const float* __restrict__ asrc, const float* __restrict__ adst, int n)
{
    int w = (blockIdx.x * blockDim.x + threadIdx.x) >> 5;
    int lane = threadIdx.x & 31;
    if (w >= 2 * n) return;
    int b = w / n;
    int loc = w - b * n;
    float4 hv = *(const float4*)(g_h2 + ((size_t)b * NN + loc) * 128 + lane * 4);
    float4 sa = *(const float4*)(asrc + lane * 4);
    float4 da = *(const float4*)(adst + lane * 4);
    float ss = hv.x * sa.x + hv.y * sa.y + hv.z * sa.z + hv.w * sa.w;
    float dd = hv.x * da.x + hv.y * da.y + hv.z * da.z + hv.w * da.w;
    #pragma unroll
    for (int o = 16; o; o >>= 1) {
        ss += __shfl_down_sync(0xffffffffu, ss, o);
        dd += __shfl_down_sync(0xffffffffu, dd, o);
    }
    if (lane == 0) { g_s2[b * NN + loc] = ss; g_d2[b * NN + loc] = dd; }
}

// ---------------- layer-1 softmax + aggregation ----------------
__global__ __launch_bounds__(256) void agg_l1_csr(int E, int Ncnt,
                                                  float* __restrict__ out, long long out_size)
{
    int b = blockIdx.y;
    int dst = (blockIdx.x * blockDim.x + threadIdx.x) >> 5;
    int lane = threadIdx.x & 31;
    if (dst >= Ncnt) return;
    const int Etot = E + Ncnt;
    const int* off  = g_off + b * (NN + 1);
    const int* eidv = g_eid + b * ETOTM;
    const int* srcv = g_esrc + b * ETOTM;
    const float* s1 = g_s1 + b * NN * 3;
    float* e0p = g_exp1 + (size_t)(b * 3 + 0) * ETOTM;
    float* e1p = g_exp1 + (size_t)(b * 3 + 1) * ETOTM;
    float* e2p = g_exp1 + (size_t)(b * 3 + 2) * ETOTM;
    const long long alpha_base = 1 + (long long)b * Etot * 3;

    int beg = off[dst], end = off[dst + 1];
    float dv0 = g_d1[b * NN * 3 + dst * 3 + 0];
    float dv1 = g_d1[b * NN * 3 + dst * 3 + 1];
    float dv2 = g_d1[b * NN * 3 + dst * 3 + 2];

    float den0 = 0.f, den1 = 0.f, den2 = 0.f;
    for (int i = beg + lane; i < end; i += 32) {
        int src = srcv[i];
        float e0 = s1[src * 3 + 0] + dv0;
        float e1 = s1[src * 3 + 1] + dv1;
        float e2 = s1[src * 3 + 2] + dv2;
        e0 = e0 > 0.f ? e0 : 0.2f * e0;
        e1 = e1 > 0.f ? e1 : 0.2f * e1;
        e2 = e2 > 0.f ? e2 : 0.2f * e2;
        float x0 = expf(e0), x1 = expf(e1), x2 = expf(e2);
        e0p[i] = x0; e1p[i] = x1; e2p[i] = x2;
        den0 += x0; den1 += x1; den2 += x2;
    }
    #pragma unroll
    for (int o = 16; o; o >>= 1) {
        den0 += __shfl_xor_sync(0xffffffffu, den0, o);
        den1 += __shfl_xor_sync(0xffffffffu, den1, o);
        den2 += __shfl_xor_sync(0xffffffffu, den2, o);
    }
    float r0 = 1.f / den0, r1 = 1.f / den1, r2 = 1.f / den2;
    __syncwarp();

    float nat = 0.f;
    for (int i = beg + lane; i < end; i += 32) {
        float a0 = e0p[i] * r0, a1 = e1p[i] * r1, a2 = e2p[i] * r2;
        long long ob = alpha_base + 3LL * eidv[i];
        if (ob + 2 < out_size) { out[ob] = a0; out[ob + 1] = a1; out[ob + 2] = a2; }
        nat += (a0 + a1 + a2) * (1.0f / 3.0f);
    }
    #pragma unroll
    for (int o = 16; o; o >>= 1) nat += __shfl_xor_sync(0xffffffffu, nat, o);
    if (lane == 0) g_nattn[b * NN + dst] = nat;

    float acc[12];
    #pragma unroll
    for (int k = 0; k < 12; k++) acc[k] = 0.f;
    const float4* h1b = (const float4*)(g_h1 + (size_t)b * NN * 384);

    #pragma unroll 2
    for (int i = beg; i < end; i++) {
        float a0 = e0p[i] * r0, a1 = e1p[i] * r1, a2 = e2p[i] * r2;
        int src = srcv[i];
        const float4* hs = h1b + (size_t)src * 96;
        float4 v0 = hs[lane];
        float4 v1 = hs[32 + lane];
        float4 v2 = hs[64 + lane];
        acc[0] += v0.x * a0; acc[1]  += v0.y * a0; acc[2]  += v0.z * a0; acc[3]  += v0.w * a0;
        acc[4] += v1.x * a1; acc[5]  += v1.y * a1; acc[6]  += v1.z * a1; acc[7]  += v1.w * a1;
        acc[8] += v2.x * a2; acc[9]  += v2.y * a2; acc[10] += v2.z * a2; acc[11] += v2.w * a2;
    }

    float4* og = (float4*)(g_agg1 + ((size_t)b * NN + dst) * 384);
    og[lane]      = make_float4(acc[0], acc[1], acc[2], acc[3]);
    og[32 + lane] = make_float4(acc[4], acc[5], acc[6], acc[7]);
    og[64 + lane] = make_float4(acc[8], acc[9], acc[10], acc[11]);
}

// ---------------- layer-2 softmax + aggregation ----------------
__global__ __launch_bounds__(256) void agg_l2_csr(int E, int Ncnt)
{
    int b = blockIdx.y;
    int dst = (blockIdx.x * blockDim.x + threadIdx.x) >> 5;
    int lane = threadIdx.x & 31;
    if (dst >= Ncnt) return;
    const int* off  = g_off + b * (NN + 1);
    const int* srcv = g_esrc + b * ETOTM;
    const float* s2 = g_s2 + b * NN;
    float* xp = g_exp2 + (size_t)b * ETOTM;

    int beg = off[dst], end = off[dst + 1];
    float dv = g_d2[b * NN + dst];
    float den = 0.f;
    for (int i = beg + lane; i < end; i += 32) {
        int src = srcv[i];
        float e = s2[src] + dv;
        e = e > 0.f ? e : 0.2f * e;
        float x = expf(e);
        xp[i] = x;
        den += x;
    }
    #pragma unroll
    for (int o = 16; o; o >>= 1) den += __shfl_xor_sync(0xffffffffu, den, o);
    float r = 1.f / den;
    __syncwarp();

    float4 acc = make_float4(0.f, 0.f, 0.f, 0.f);
    const float4* h2b = (const float4*)(g_h2 + (size_t)b * NN * 128);
    #pragma unroll 2
    for (int i = beg; i < end; i++) {
        float a = xp[i] * r;
        int src = srcv[i];
        float4 v = h2b[(size_t)src * 32 + lane];
        acc.x += v.x * a; acc.y += v.y * a; acc.z += v.z * a; acc.w += v.w * a;
    }
    ((float4*)(g_agg2 + ((size_t)b * NN + dst) * 128))[lane] = acc;
}

// ---------------- pooling: grid (128, 2) ----------------
__global__ void pool_kernel(const float* __restrict__ b2, int Ncnt)
{
    int c = blockIdx.x;
    int b = blockIdx.y;
    const float* ag = g_agg2 + (size_t)b * NN * 128;
    const float* na = g_nattn + b * NN;
    float bias = b2[c];
    float sw = 0.f, se = 0.f;
    for (int n = threadIdx.x; n < Ncnt; n += blockDim.x) {
        float v = ag[(size_t)n * 128 + c] + bias;
        se += v;
        sw += v * na[n];
    }
    __shared__ float r0[256], r1[256];
    r0[threadIdx.x] = sw; r1[threadIdx.x] = se;
    __syncthreads();
    for (int o = 128; o; o >>= 1) {
        if (threadIdx.x < o) { r0[threadIdx.x] += r0[threadIdx.x + o]; r1[threadIdx.x] += r1[threadIdx.x + o]; }
        __syncthreads();
    }
    if (threadIdx.x == 0) {
        float inv = 1.0f / (float)Ncnt;
        g_pool[b * 256 + c]       = r0[0] * inv;
        g_pool[b * 256 + 128 + c] = r1[0] * inv;
    }
}

// ---------------- cosine similarity ----------------
__global__ void sim_kernel(float* __restrict__ out, long long out_size)
{
    int t = threadIdx.x;
    float a = g_pool[t], b = g_pool[256 + t];
    __shared__ float sd_[256], sa[256], sb[256];
    sd_[t] = a * b; sa[t] = a * a; sb[t] = b * b;
    __syncthreads();
    for (int o = 128; o; o >>= 1) {
        if (t < o) { sd_[t] += sd_[t + o]; sa[t] += sa[t + o]; sb[t] += sb[t + o]; }
        __syncthreads();
    }
    if (t == 0 && out_size >= 1) {
        float n1 = fmaxf(sqrtf(sa[0]), 1e-8f);
        float n2 = fmaxf(sqrtf(sb[0]), 1e-8f);
        out[0] = sd_[0] / (n1 * n2);
    }
}

// ---------------- host launcher ----------------
extern "C" void kernel_launch(void* const* d_in, const int* in_sizes, int n_in,
                              void* d_out, int out_size)
{
    const float* x1  = (const float*)d_in[0];
    const int*   ei1 = (const int*)d_in[1];     // int32
    const float* x2  = (const float*)d_in[2];
    const int*   ei2 = (const int*)d_in[3];
    const float* W1  = (const float*)d_in[4];
    const float* as1 = (const float*)d_in[5];
    const float* ad1 = (const float*)d_in[6];
    const float* b1  = (const float*)d_in[7];
    const float* W2  = (const float*)d_in[8];
    const float* as2 = (const float*)d_in[9];
    const float* ad2 = (const float*)d_in[10];
    const float* b2  = (const float*)d_in[11];
    float* out = (float*)d_out;
    const long long osz = (long long)out_size;

    const int Ncnt = in_sizes[0] / 256;
    const int E    = in_sizes[1] / 2;
    const int Etot = E + Ncnt;

    const int e2blocks = (2 * Etot + 255) / 256;
    const int nwb = (Ncnt * 32 + 255) / 256;

    // CSR build, both branches fused
    init_deg<<<(2 * Ncnt + 255) / 256, 256>>>(Ncnt);
    csr_count<<<e2blocks, 256>>>(ei1, ei2, E, Ncnt);
    csr_scan<<<2, 1024>>>(Ncnt, Etot);
    csr_scatter<<<e2blocks, 256>>>(ei1, ei2, E, Ncnt);

    // layer 1 (both branches)
    gemm_l1<<<dim3(3, (Ncnt + 127) / 128, 2), 256>>>(x1, x2, W1, Ncnt);
    sd_l1<<<(2 * Ncnt * 3 * 32 + 255) / 256, 256>>>(as1, ad1, Ncnt);
    agg_l1_csr<<<dim3(nwb, 2), 256>>>(E, Ncnt, out, osz);

    // layer 2 (both branches)
    gemm_l2<<<dim3(2, (Ncnt + 127) / 128, 2), 256>>>(W2, b1, Ncnt);
    sd_l2<<<(2 * Ncnt * 32 + 255) / 256, 256>>>(as2, ad2, Ncnt);
    agg_l2_csr<<<dim3(nwb, 2), 256>>>(E, Ncnt);

    // pooling + similarity
    pool_kernel<<<dim3(128, 2), 256>>>(b2, Ncnt);
    sim_kernel<<<1, 256>>>(out, osz);
}